// round 1
// baseline (speedup 1.0000x reference)
#include <cuda_runtime.h>

#define NB   8
#define CIN  64
#define HID  128
#define HH   192
#define WW   192
#define PIX  (HH*WW)   /* 36864 */

// scratch (allocation-guard-safe __device__ globals)
__device__ float g_h[(size_t)NB * HID * PIX];   // 151 MB intermediate h
__device__ float g_xmean[NB * CIN];
__device__ float g_dk[NB * HID * 9];

// ---------------------------------------------------------------------------
// K1: per-(b,c) mean of x. mean(h) = W_in @ mean(x) + b_in (linearity), so we
// never reduce the 151MB h tensor.
// ---------------------------------------------------------------------------
__global__ __launch_bounds__(256) void k_xmean(const float* __restrict__ x) {
    int bc = blockIdx.x;  // 0..511
    const float4* xp = (const float4*)(x + (size_t)bc * PIX);
    float s = 0.f;
    for (int i = threadIdx.x; i < PIX / 4; i += 256) {
        float4 v = xp[i];
        s += (v.x + v.y) + (v.z + v.w);
    }
    __shared__ float red[256];
    red[threadIdx.x] = s;
    __syncthreads();
    for (int off = 128; off > 0; off >>= 1) {
        if (threadIdx.x < off) red[threadIdx.x] += red[threadIdx.x + off];
        __syncthreads();
    }
    if (threadIdx.x == 0) g_xmean[bc] = red[0] * (1.0f / PIX);
}

// ---------------------------------------------------------------------------
// K2: kernel generator. hmean -> relu(wg1) -> wg2 -> per-sample dw kernels.
// Tiny (≈1.3M FMA), single block.
// ---------------------------------------------------------------------------
__global__ __launch_bounds__(256) void k_genk(
    const float* __restrict__ w_in, const float* __restrict__ b_in,
    const float* __restrict__ wg1,  const float* __restrict__ bg1,
    const float* __restrict__ wg2,  const float* __restrict__ bg2) {
    __shared__ float hm[NB * HID];
    __shared__ float gg[NB * HID];
    int tid = threadIdx.x;
    for (int idx = tid; idx < NB * HID; idx += 256) {
        int b = idx / HID, o = idx % HID;
        float s = b_in[o];
        #pragma unroll 8
        for (int c = 0; c < CIN; c++) s += w_in[o * CIN + c] * g_xmean[b * CIN + c];
        hm[idx] = s;
    }
    __syncthreads();
    for (int idx = tid; idx < NB * HID; idx += 256) {
        int b = idx / HID, j = idx % HID;
        float s = bg1[j];
        #pragma unroll 8
        for (int o = 0; o < HID; o++) s += wg1[j * HID + o] * hm[b * HID + o];
        gg[idx] = s > 0.f ? s : 0.f;
    }
    __syncthreads();
    for (int idx = tid; idx < NB * HID * 9; idx += 256) {
        int b = idx / (HID * 9), m = idx % (HID * 9);
        float s = bg2[m];
        #pragma unroll 8
        for (int j = 0; j < HID; j++) s += wg2[m * HID + j] * gg[b * HID + j];
        g_dk[idx] = s;
    }
}

// ---------------------------------------------------------------------------
// K3: h = W_in @ x + b_in  (1x1 conv as GEMM).
// Block: 128 out-ch x 128 pixels. Thread: 16(o) x 4(px) register tile.
// Per c-iter/thread: 5 LDS.128 (broadcast weights + coalesced x) vs 64 FMA.
// ---------------------------------------------------------------------------
__global__ __launch_bounds__(256) void k_proj_in(
    const float* __restrict__ x, const float* __restrict__ w_in,
    const float* __restrict__ b_in) {
    __shared__ float xs[16 * 128];   // [c][px]
    __shared__ float wT[16 * 132];   // [c][o], padded row to dodge conflicts
    int b  = blockIdx.y;
    int p0 = blockIdx.x * 128;
    int tid = threadIdx.x;
    int tx = tid & 31;   // pixel tile 0..31 (4 px each)
    int ty = tid >> 5;   // o strip 0..7 (16 o each)

    float acc[16][4];
    #pragma unroll
    for (int i = 0; i < 16; i++) {
        float bi = __ldg(&b_in[ty * 16 + i]);
        acc[i][0] = bi; acc[i][1] = bi; acc[i][2] = bi; acc[i][3] = bi;
    }

    for (int cc = 0; cc < CIN; cc += 16) {
        __syncthreads();
        // xs: 16 x 128 floats, coalesced float4
        for (int idx = tid; idx < 512; idx += 256) {
            int c = idx >> 5;
            int pp = (idx & 31) << 2;
            *(float4*)&xs[c * 128 + pp] =
                *(const float4*)&x[(size_t)(b * CIN + cc + c) * PIX + p0 + pp];
        }
        // wT: transpose-load w_in chunk
        for (int idx = tid; idx < 2048; idx += 256) {
            int c = idx & 15, o = idx >> 4;
            wT[c * 132 + o] = w_in[o * CIN + cc + c];
        }
        __syncthreads();

        #pragma unroll
        for (int c = 0; c < 16; c++) {
            float4 xv = *(const float4*)&xs[c * 128 + (tx << 2)];
            float xr[4] = {xv.x, xv.y, xv.z, xv.w};
            #pragma unroll
            for (int q = 0; q < 4; q++) {
                float4 wv = *(const float4*)&wT[c * 132 + ty * 16 + q * 4];
                float wr[4] = {wv.x, wv.y, wv.z, wv.w};
                #pragma unroll
                for (int i = 0; i < 4; i++)
                    #pragma unroll
                    for (int j = 0; j < 4; j++)
                        acc[q * 4 + i][j] += wr[i] * xr[j];
            }
        }
    }

    #pragma unroll
    for (int i = 0; i < 16; i++) {
        float4 v = make_float4(acc[i][0], acc[i][1], acc[i][2], acc[i][3]);
        *(float4*)&g_h[(size_t)(b * HID + ty * 16 + i) * PIX + p0 + (tx << 2)] = v;
    }
}

// ---------------------------------------------------------------------------
// K4: fused depthwise 3x3 (per-sample kernels) + LeakyReLU(0.1) + W_out GEMM.
// Block: one sample, 32x8 output pixels. Channel-chunked (16) through smem:
//   hs (halo tile) -> dw/leaky -> ylc -> 8(o) x 8(px) register-tile GEMM
//   with 64 persistent accumulators per thread.
// ---------------------------------------------------------------------------
__global__ __launch_bounds__(256) void k_dw_out(
    const float* __restrict__ w_out, const float* __restrict__ b_out,
    float* __restrict__ out) {
    extern __shared__ float sm[];
    float* wt  = sm;                    // [128][68]  w_out transposed, padded
    float* hs  = wt + 128 * 68;         // [16][344]  h halo tile (34x10 used)
    float* ylc = hs + 16 * 344;         // [16][264]  leaky(dwconv) chunk
    float* dks = ylc + 16 * 264;        // [128*9]    per-sample dw kernels

    int b   = blockIdx.z;
    int tx0 = blockIdx.x * 32;
    int ty0 = blockIdx.y * 8;
    int tid = threadIdx.x;

    // one-time loads
    for (int idx = tid; idx < 64 * 128; idx += 256) {
        int c = idx >> 6, o = idx & 63;
        wt[c * 68 + o] = w_out[o * 128 + c];
    }
    for (int idx = tid; idx < 128 * 9; idx += 256)
        dks[idx] = g_dk[b * HID * 9 + idx];

    int lx = tid & 31;   // out px strip: pbase = lx*8
    int ly = tid >> 5;   // out o  strip: obase = ly*8
    float acc[8][8];
    #pragma unroll
    for (int i = 0; i < 8; i++)
        #pragma unroll
        for (int j = 0; j < 8; j++) acc[i][j] = 0.f;

    int dc = tid >> 4;   // dw: channel within chunk (0..15)
    int pj = tid & 15;   // dw: pixel phase
    __syncthreads();

    for (int cc = 0; cc < HID; cc += 16) {
        // load h halo tile (zero-padded SAME)
        for (int idx = tid; idx < 16 * 340; idx += 256) {
            int c = idx / 340, hp = idx % 340;
            int hy = hp / 34, hx = hp % 34;
            int gy = ty0 + hy - 1, gx = tx0 + hx - 1;
            float v = 0.f;
            if (gy >= 0 && gy < HH && gx >= 0 && gx < WW)
                v = g_h[(size_t)(b * HID + cc + c) * PIX + gy * WW + gx];
            hs[c * 344 + hp] = v;
        }
        __syncthreads();

        // depthwise 3x3 + leaky -> ylc. dk regs amortized over 16 px.
        {
            float kr[9];
            #pragma unroll
            for (int j = 0; j < 9; j++) kr[j] = dks[(cc + dc) * 9 + j];
            const float* hc = &hs[dc * 344];
            #pragma unroll
            for (int i = 0; i < 16; i++) {
                int px  = pj + (i << 4);
                int py  = px >> 5, pxx = px & 31;
                int hp  = (py + 1) * 34 + (pxx + 1);
                float y =
                    kr[0] * hc[hp - 35] + kr[1] * hc[hp - 34] + kr[2] * hc[hp - 33] +
                    kr[3] * hc[hp - 1]  + kr[4] * hc[hp]      + kr[5] * hc[hp + 1]  +
                    kr[6] * hc[hp + 33] + kr[7] * hc[hp + 34] + kr[8] * hc[hp + 35];
                ylc[dc * 264 + px] = y > 0.f ? y : 0.1f * y;
            }
        }
        __syncthreads();

        // out-projection accumulate: per c, 4 LDS.128 vs 64 FMA
        #pragma unroll
        for (int c = 0; c < 16; c++) {
            float4 w0 = *(const float4*)&wt[(cc + c) * 68 + ly * 8];
            float4 w1 = *(const float4*)&wt[(cc + c) * 68 + ly * 8 + 4];
            float4 y0 = *(const float4*)&ylc[c * 264 + lx * 8];
            float4 y1 = *(const float4*)&ylc[c * 264 + lx * 8 + 4];
            float wr[8] = {w0.x, w0.y, w0.z, w0.w, w1.x, w1.y, w1.z, w1.w};
            float yr[8] = {y0.x, y0.y, y0.z, y0.w, y1.x, y1.y, y1.z, y1.w};
            #pragma unroll
            for (int i = 0; i < 8; i++)
                #pragma unroll
                for (int j = 0; j < 8; j++)
                    acc[i][j] += wr[i] * yr[j];
        }
        __syncthreads();
    }

    // write out (+b_out)
    #pragma unroll
    for (int i = 0; i < 8; i++) {
        int o = ly * 8 + i;
        float bo = __ldg(&b_out[o]);
        int px  = lx * 8;
        int py  = px >> 5, pxx = px & 31;
        size_t base = (size_t)(b * CIN + o) * PIX + (ty0 + py) * WW + tx0 + pxx;
        float4 v0 = make_float4(acc[i][0] + bo, acc[i][1] + bo,
                                acc[i][2] + bo, acc[i][3] + bo);
        float4 v1 = make_float4(acc[i][4] + bo, acc[i][5] + bo,
                                acc[i][6] + bo, acc[i][7] + bo);
        *(float4*)&out[base]     = v0;
        *(float4*)&out[base + 4] = v1;
    }
}

// ---------------------------------------------------------------------------
extern "C" void kernel_launch(void* const* d_in, const int* in_sizes, int n_in,
                              void* d_out, int out_size) {
    const float* x     = (const float*)d_in[0];
    const float* w_in  = (const float*)d_in[1];
    const float* b_in  = (const float*)d_in[2];
    const float* wg1   = (const float*)d_in[3];
    const float* bg1   = (const float*)d_in[4];
    const float* wg2   = (const float*)d_in[5];
    const float* bg2   = (const float*)d_in[6];
    const float* w_out = (const float*)d_in[7];
    const float* b_out = (const float*)d_in[8];
    float* out = (float*)d_out;

    k_xmean<<<NB * CIN, 256>>>(x);
    k_genk<<<1, 256>>>(w_in, b_in, wg1, bg1, wg2, bg2);
    k_proj_in<<<dim3(PIX / 128, NB), 256>>>(x, w_in, b_in);

    int smem = (128 * 68 + 16 * 344 + 16 * 264 + 128 * 9) * 4;  // 78336 B
    cudaFuncSetAttribute(k_dw_out, cudaFuncAttributeMaxDynamicSharedMemorySize, smem);
    k_dw_out<<<dim3(WW / 32, HH / 8, NB), 256, smem>>>(w_out, b_out, out);
}

// round 2
// speedup vs baseline: 1.3155x; 1.3155x over previous
#include <cuda_runtime.h>

#define NB   8
#define CIN  64
#define HID  128
#define HH   192
#define WW   192
#define PIX  (HH*WW)   /* 36864 */

// scratch (allocation-guard-safe __device__ globals)
__device__ float g_xmean[NB * CIN];
__device__ float g_gg[NB * HID];
__device__ float g_dk[NB * HID * 9];

// ---------------------------------------------------------------------------
// K1: per-(b,c) mean of x. mean(h) = W_in @ mean(x) + b_in (linearity).
// ---------------------------------------------------------------------------
__global__ __launch_bounds__(256) void k_xmean(const float* __restrict__ x) {
    int bc = blockIdx.x;  // 0..511
    const float4* xp = (const float4*)(x + (size_t)bc * PIX);
    float s = 0.f;
    for (int i = threadIdx.x; i < PIX / 4; i += 256) {
        float4 v = xp[i];
        s += (v.x + v.y) + (v.z + v.w);
    }
    __shared__ float red[256];
    red[threadIdx.x] = s;
    __syncthreads();
    for (int off = 128; off > 0; off >>= 1) {
        if (threadIdx.x < off) red[threadIdx.x] += red[threadIdx.x + off];
        __syncthreads();
    }
    if (threadIdx.x == 0) g_xmean[bc] = red[0] * (1.0f / PIX);
}

// ---------------------------------------------------------------------------
// K2a: hmean -> relu(wg1 @ hmean + bg1) = gg. Tiny, 1 block.
// ---------------------------------------------------------------------------
__global__ __launch_bounds__(256) void k_genAB(
    const float* __restrict__ w_in, const float* __restrict__ b_in,
    const float* __restrict__ wg1,  const float* __restrict__ bg1) {
    __shared__ float hm[NB * HID];
    int tid = threadIdx.x;
    for (int idx = tid; idx < NB * HID; idx += 256) {
        int b = idx / HID, o = idx % HID;
        float s = b_in[o];
        #pragma unroll 16
        for (int c = 0; c < CIN; c++) s += w_in[o * CIN + c] * g_xmean[b * CIN + c];
        hm[idx] = s;
    }
    __syncthreads();
    for (int idx = tid; idx < NB * HID; idx += 256) {
        int b = idx / HID, j = idx % HID;
        float s = bg1[j];
        const float4* wr = (const float4*)&wg1[j * HID];
        const float4* hr = (const float4*)&hm[b * HID];
        #pragma unroll 8
        for (int o = 0; o < HID / 4; o++) {
            float4 w = wr[o], h = hr[o];
            s += w.x * h.x + w.y * h.y + w.z * h.z + w.w * h.w;
        }
        g_gg[idx] = s > 0.f ? s : 0.f;
    }
}

// ---------------------------------------------------------------------------
// K2b: dk = wg2 @ gg + bg2 — the 1.2M-FMA stage, now 32 blocks (was 1).
// grid (4, NB) x 288 threads; each thread one output row of wg2.
// ---------------------------------------------------------------------------
__global__ __launch_bounds__(288) void k_genC(
    const float* __restrict__ wg2, const float* __restrict__ bg2) {
    __shared__ float ggs[HID];
    int b = blockIdx.y;
    int tid = threadIdx.x;
    if (tid < HID) ggs[tid] = g_gg[b * HID + tid];
    __syncthreads();
    int m = blockIdx.x * 288 + tid;   // 0..1151
    float s = bg2[m];
    const float4* wr = (const float4*)&wg2[(size_t)m * HID];
    #pragma unroll 8
    for (int j = 0; j < HID / 4; j++) {
        float4 w = wr[j];
        float4 g = *(const float4*)&ggs[j * 4];
        s += w.x * g.x + w.y * g.y + w.z * g.z + w.w * g.w;
    }
    g_dk[b * HID * 9 + m] = s;
}

// ---------------------------------------------------------------------------
// K3: fully fused  h = W_in@x  ->  per-sample depthwise 3x3 + LeakyReLU
//                 ->  out = W_out@y + b_out.
// One block = one 32x8 output tile of one sample. x halo tile (64ch x 34x10)
// resident in smem; h computed per 32-channel chunk into smem (halo coords),
// dw'd, then accumulated into 64 persistent per-thread out accumulators.
// g_h intermediate eliminated (saves ~350MB DRAM round-trip).
// ---------------------------------------------------------------------------
#define XROW 344   /* 34*10=340 used, padded */
#define YROW 264   /* 256 used, padded */
#define CHK  32

__global__ __launch_bounds__(256) void k_fused(
    const float* __restrict__ x, const float* __restrict__ w_in,
    const float* __restrict__ b_in, const float* __restrict__ w_out,
    const float* __restrict__ b_out, float* __restrict__ out) {
    extern __shared__ float sm[];
    float* xs  = sm;                    // [64][344]  x halo tile
    float* wsT = xs  + 64 * XROW;       // [64][36]   w_in chunk, [cin][hid]
    float* wt  = wsT + 64 * 36;         // [128][68]  w_out^T
    float* dks = wt  + 128 * 68;        // [1152]     per-sample dw kernels
    float* hsm = dks + 1152;            // [32][344]  h chunk (halo coords)
    float* ylc = hsm + CHK * XROW;      // [32][264]  leaky(dw) chunk

    int b   = blockIdx.z;
    int tx0 = blockIdx.x * 32;
    int ty0 = blockIdx.y * 8;
    int tid = threadIdx.x;

    // one-time loads: w_out^T, dw kernels, x halo tile
    for (int idx = tid; idx < CIN * HID; idx += 256) {
        int c = idx >> 6, o = idx & 63;
        wt[c * 68 + o] = w_out[o * HID + c];
    }
    for (int idx = tid; idx < HID * 9; idx += 256)
        dks[idx] = g_dk[b * HID * 9 + idx];
    for (int idx = tid; idx < 64 * 340; idx += 256) {
        int c = idx / 340, hp = idx - c * 340;
        int hy = hp / 34,  hx = hp - hy * 34;
        int gy = ty0 + hy - 1, gx = tx0 + hx - 1;
        float v = 0.f;
        if (gy >= 0 && gy < HH && gx >= 0 && gx < WW)
            v = x[(size_t)(b * CIN + c) * PIX + gy * WW + gx];
        xs[c * XROW + hp] = v;
    }

    int lx = tid & 31;      // out-proj: pixel strip (8 px)
    int ly = tid >> 5;      // out-proj: o strip (8 o)
    int dc = tid >> 3;      // dw: channel in chunk (0..31)
    int pj = tid & 7;       // dw: pixel phase
    float acc[8][8];
    #pragma unroll
    for (int i = 0; i < 8; i++)
        #pragma unroll
        for (int j = 0; j < 8; j++) acc[i][j] = 0.f;

    for (int cc = 0; cc < HID; cc += CHK) {
        __syncthreads();
        // w_in chunk, transposed: wsT[cin][ch]
        for (int idx = tid; idx < 64 * CHK; idx += 256) {
            int ch = idx & 31, c = idx >> 5;
            wsT[c * 36 + ch] = w_in[(cc + ch) * CIN + c];
        }
        __syncthreads();

        // ---- h GEMM on halo grid: 32ch x 340px, reg tile 4ch x 4px ----
        {
            int hty = tid >> 5;          // 8 groups of 4 channels
            #pragma unroll
            for (int pass = 0; pass < 3; pass++) {
                int pg = (tid & 31) + pass * 32;   // float4 group, < 85
                if (pg < 85) {
                    int px = pg << 2;
                    float hacc[4][4];
                    #pragma unroll
                    for (int i = 0; i < 4; i++) {
                        float bi = __ldg(&b_in[cc + hty * 4 + i]);
                        hacc[i][0] = bi; hacc[i][1] = bi;
                        hacc[i][2] = bi; hacc[i][3] = bi;
                    }
                    #pragma unroll 8
                    for (int c = 0; c < CIN; c++) {
                        float4 xv = *(const float4*)&xs[c * XROW + px];
                        float4 wv = *(const float4*)&wsT[c * 36 + hty * 4];
                        float xr[4] = {xv.x, xv.y, xv.z, xv.w};
                        float wr[4] = {wv.x, wv.y, wv.z, wv.w};
                        #pragma unroll
                        for (int i = 0; i < 4; i++)
                            #pragma unroll
                            for (int j = 0; j < 4; j++)
                                hacc[i][j] += wr[i] * xr[j];
                    }
                    #pragma unroll
                    for (int i = 0; i < 4; i++)
                        *(float4*)&hsm[(hty * 4 + i) * XROW + px] =
                            make_float4(hacc[i][0], hacc[i][1], hacc[i][2], hacc[i][3]);
                }
            }
        }
        __syncthreads();

        // ---- depthwise 3x3 + LeakyReLU(0.1) -> ylc ----
        {
            float kr[9];
            #pragma unroll
            for (int j = 0; j < 9; j++) kr[j] = dks[(cc + dc) * 9 + j];
            const float* hc = &hsm[dc * XROW];
            #pragma unroll
            for (int i = 0; i < 32; i++) {
                int px  = pj + (i << 3);
                int py  = px >> 5, pxx = px & 31;
                int hp  = (py + 1) * 34 + pxx + 1;
                float y =
                    kr[0] * hc[hp - 35] + kr[1] * hc[hp - 34] + kr[2] * hc[hp - 33] +
                    kr[3] * hc[hp - 1]  + kr[4] * hc[hp]      + kr[5] * hc[hp + 1]  +
                    kr[6] * hc[hp + 33] + kr[7] * hc[hp + 34] + kr[8] * hc[hp + 35];
                ylc[dc * YROW + px] = y > 0.f ? y : 0.1f * y;
            }
        }
        __syncthreads();

        // ---- out-projection accumulate: 8o x 8px reg tile ----
        #pragma unroll 4
        for (int c = 0; c < CHK; c++) {
            float4 w0 = *(const float4*)&wt[(cc + c) * 68 + ly * 8];
            float4 w1 = *(const float4*)&wt[(cc + c) * 68 + ly * 8 + 4];
            float4 y0 = *(const float4*)&ylc[c * YROW + lx * 8];
            float4 y1 = *(const float4*)&ylc[c * YROW + lx * 8 + 4];
            float wr[8] = {w0.x, w0.y, w0.z, w0.w, w1.x, w1.y, w1.z, w1.w};
            float yr[8] = {y0.x, y0.y, y0.z, y0.w, y1.x, y1.y, y1.z, y1.w};
            #pragma unroll
            for (int i = 0; i < 8; i++)
                #pragma unroll
                for (int j = 0; j < 8; j++)
                    acc[i][j] += wr[i] * yr[j];
        }
    }

    // write out (+b_out)
    #pragma unroll
    for (int i = 0; i < 8; i++) {
        int o = ly * 8 + i;
        float bo = __ldg(&b_out[o]);
        int px  = lx * 8;
        int py  = px >> 5, pxx = px & 31;
        size_t base = (size_t)(b * CIN + o) * PIX + (ty0 + py) * WW + tx0 + pxx;
        *(float4*)&out[base]     = make_float4(acc[i][0] + bo, acc[i][1] + bo,
                                               acc[i][2] + bo, acc[i][3] + bo);
        *(float4*)&out[base + 4] = make_float4(acc[i][4] + bo, acc[i][5] + bo,
                                               acc[i][6] + bo, acc[i][7] + bo);
    }
}

// ---------------------------------------------------------------------------
extern "C" void kernel_launch(void* const* d_in, const int* in_sizes, int n_in,
                              void* d_out, int out_size) {
    const float* x     = (const float*)d_in[0];
    const float* w_in  = (const float*)d_in[1];
    const float* b_in  = (const float*)d_in[2];
    const float* wg1   = (const float*)d_in[3];
    const float* bg1   = (const float*)d_in[4];
    const float* wg2   = (const float*)d_in[5];
    const float* bg2   = (const float*)d_in[6];
    const float* w_out = (const float*)d_in[7];
    const float* b_out = (const float*)d_in[8];
    float* out = (float*)d_out;

    k_xmean<<<NB * CIN, 256>>>(x);
    k_genAB<<<1, 256>>>(w_in, b_in, wg1, bg1);
    k_genC<<<dim3(4, NB), 288>>>(wg2, bg2);

    int smem = (64 * XROW + 64 * 36 + 128 * 68 + 1152 +
                CHK * XROW + CHK * YROW) * 4;   // 214528 B
    cudaFuncSetAttribute(k_fused, cudaFuncAttributeMaxDynamicSharedMemorySize, smem);
    k_fused<<<dim3(WW / 32, HH / 8, NB), 256, smem>>>(
        x, w_in, b_in, w_out, b_out, out);
}

// round 3
// speedup vs baseline: 2.2378x; 1.7011x over previous
#include <cuda_runtime.h>

#define NB   8
#define CIN  64
#define HID  128
#define HH   192
#define WW   192
#define PIX  (HH*WW)   /* 36864 */

typedef unsigned long long u64;

__device__ __forceinline__ u64 pack2(float lo, float hi) {
    u64 d;
    asm("mov.b64 %0, {%1,%2};" : "=l"(d)
        : "r"(__float_as_uint(lo)), "r"(__float_as_uint(hi)));
    return d;
}
__device__ __forceinline__ void unpack2(u64 v, float& lo, float& hi) {
    unsigned a, b;
    asm("mov.b64 {%0,%1}, %2;" : "=r"(a), "=r"(b) : "l"(v));
    lo = __uint_as_float(a); hi = __uint_as_float(b);
}
__device__ __forceinline__ u64 ffma2(u64 a, u64 b, u64 c) {
    u64 d;
    asm("fma.rn.f32x2 %0, %1, %2, %3;" : "=l"(d) : "l"(a), "l"(b), "l"(c));
    return d;
}

// scratch (allocation-guard-safe __device__ globals)
__device__ float g_xmean[NB * CIN];
__device__ float g_gg[NB * HID];
__device__ float g_dk[NB * HID * 9];

// ---------------------------------------------------------------------------
// K1: per-(b,c) mean of x (mean(h) = W_in @ mean(x) + b_in by linearity).
// ---------------------------------------------------------------------------
__global__ __launch_bounds__(256) void k_xmean(const float* __restrict__ x) {
    int bc = blockIdx.x;
    const float4* xp = (const float4*)(x + (size_t)bc * PIX);
    float s = 0.f;
    for (int i = threadIdx.x; i < PIX / 4; i += 256) {
        float4 v = xp[i];
        s += (v.x + v.y) + (v.z + v.w);
    }
    __shared__ float red[256];
    red[threadIdx.x] = s;
    __syncthreads();
    for (int off = 128; off > 0; off >>= 1) {
        if (threadIdx.x < off) red[threadIdx.x] += red[threadIdx.x + off];
        __syncthreads();
    }
    if (threadIdx.x == 0) g_xmean[bc] = red[0] * (1.0f / PIX);
}

// ---------------------------------------------------------------------------
// K2a: hmean -> relu(wg1 @ hmean + bg1) = gg. Tiny, 1 block.
// ---------------------------------------------------------------------------
__global__ __launch_bounds__(256) void k_genAB(
    const float* __restrict__ w_in, const float* __restrict__ b_in,
    const float* __restrict__ wg1,  const float* __restrict__ bg1) {
    __shared__ float hm[NB * HID];
    int tid = threadIdx.x;
    for (int idx = tid; idx < NB * HID; idx += 256) {
        int b = idx / HID, o = idx % HID;
        float s = b_in[o];
        #pragma unroll 16
        for (int c = 0; c < CIN; c++) s += w_in[o * CIN + c] * g_xmean[b * CIN + c];
        hm[idx] = s;
    }
    __syncthreads();
    for (int idx = tid; idx < NB * HID; idx += 256) {
        int b = idx / HID, j = idx % HID;
        float s = bg1[j];
        const float4* wr = (const float4*)&wg1[j * HID];
        const float4* hr = (const float4*)&hm[b * HID];
        #pragma unroll 8
        for (int o = 0; o < HID / 4; o++) {
            float4 w = wr[o], h = hr[o];
            s += w.x * h.x + w.y * h.y + w.z * h.z + w.w * h.w;
        }
        g_gg[idx] = s > 0.f ? s : 0.f;
    }
}

// ---------------------------------------------------------------------------
// K2b: dk = wg2 @ gg + bg2. 36 blocks; wg2 staged coalesced; read once.
// ---------------------------------------------------------------------------
__global__ __launch_bounds__(256) void k_genC(
    const float* __restrict__ wg2, const float* __restrict__ bg2) {
    __shared__ float w2s[32 * 128];
    __shared__ float ggs[NB * HID];
    int tid = threadIdx.x;
    int m0 = blockIdx.x * 32;
    for (int idx = tid; idx < 32 * 128 / 4; idx += 256)
        *(float4*)&w2s[idx * 4] = *(const float4*)&wg2[(size_t)m0 * HID + idx * 4];
    for (int idx = tid; idx < NB * HID / 4; idx += 256)
        *(float4*)&ggs[idx * 4] = *(const float4*)&g_gg[idx * 4];
    __syncthreads();
    int ml = tid >> 3, b = tid & 7;
    float s = bg2[m0 + ml];
    #pragma unroll 8
    for (int j = 0; j < HID / 4; j++) {
        float4 w = *(const float4*)&w2s[ml * 128 + j * 4];
        float4 g = *(const float4*)&ggs[b * HID + j * 4];
        s += w.x * g.x + w.y * g.y + w.z * g.z + w.w * g.w;
    }
    g_dk[b * HID * 9 + m0 + ml] = s;
}

// ---------------------------------------------------------------------------
// K3: fused h=W_in@x -> per-sample dw3x3 + LeakyReLU -> out=W_out@y + b_out.
// 512 threads/block (16 warps/SM), f32x2 packed FMA in both GEMMs.
// ---------------------------------------------------------------------------
#define XROW 344   /* 34*10=340 used */
#define YROW 264   /* 256 used */
#define CHK  32

__global__ __launch_bounds__(512) void k_fused(
    const float* __restrict__ x, const float* __restrict__ w_in,
    const float* __restrict__ b_in, const float* __restrict__ w_out,
    const float* __restrict__ b_out, float* __restrict__ out) {
    extern __shared__ float sm[];
    float* xs  = sm;                    // [64][344]  x halo tile
    float* wsT = xs  + 64 * XROW;       // [64][36]   w_in chunk^T
    float* wt  = wsT + 64 * 36;         // [128][68]  w_out^T
    float* dks = wt  + 128 * 68;        // [1152]
    float* hsm = dks + 1152;            // [32][344]
    float* ylc = hsm + CHK * XROW;      // [32][264]

    int b   = blockIdx.z;
    int tx0 = blockIdx.x * 32;
    int ty0 = blockIdx.y * 8;
    int tid = threadIdx.x;

    // one-time loads
    for (int idx = tid; idx < CIN * HID; idx += 512) {
        int c = idx >> 6, o = idx & 63;
        wt[c * 68 + o] = w_out[o * HID + c];
    }
    for (int idx = tid; idx < HID * 9; idx += 512)
        dks[idx] = g_dk[b * HID * 9 + idx];
    for (int idx = tid; idx < 64 * 340; idx += 512) {
        int c = idx / 340, hp = idx - c * 340;
        int hy = hp / 34,  hx = hp - hy * 34;
        int gy = ty0 + hy - 1, gx = tx0 + hx - 1;
        float v = 0.f;
        if (gy >= 0 && gy < HH && gx >= 0 && gx < WW)
            v = x[(size_t)(b * CIN + c) * PIX + gy * WW + gx];
        xs[c * XROW + hp] = v;
    }

    int lx = tid & 63;      // out-proj: 4-px strip (conflict-free float4)
    int ly = tid >> 6;      // out-proj: 8-o strip
    int hty = tid >> 6;     // h-GEMM: 4-channel group
    int l64 = tid & 63;
    int lane = tid & 31, wrp = tid >> 5;

    u64 acc2[4][4];         // o-pairs x px, packed f32x2
    #pragma unroll
    for (int i = 0; i < 4; i++)
        #pragma unroll
        for (int j = 0; j < 4; j++) acc2[i][j] = 0ULL;

    for (int cc = 0; cc < HID; cc += CHK) {
        __syncthreads();
        // w_in chunk transposed (coalesced LDG)
        for (int idx = tid; idx < 64 * CHK; idx += 512) {
            int c = idx & 63, ch = idx >> 6;
            wsT[c * 36 + ch] = w_in[(cc + ch) * CIN + c];
        }
        __syncthreads();

        // ---- h GEMM on halo grid, f32x2 (px-pairs) ----
        #pragma unroll
        for (int pass = 0; pass < 2; pass++) {
            int pg = l64 + pass * 64;
            if (pg < 85) {
                int px = pg << 2;
                u64 hacc[4][2];
                #pragma unroll
                for (int i = 0; i < 4; i++) {
                    float bi = __ldg(&b_in[cc + hty * 4 + i]);
                    hacc[i][0] = pack2(bi, bi);
                    hacc[i][1] = hacc[i][0];
                }
                #pragma unroll 8
                for (int c = 0; c < CIN; c++) {
                    float4 xv = *(const float4*)&xs[c * XROW + px];
                    u64 x01 = pack2(xv.x, xv.y);
                    u64 x23 = pack2(xv.z, xv.w);
                    float4 wv = *(const float4*)&wsT[c * 36 + hty * 4];
                    u64 w;
                    w = pack2(wv.x, wv.x);
                    hacc[0][0] = ffma2(w, x01, hacc[0][0]);
                    hacc[0][1] = ffma2(w, x23, hacc[0][1]);
                    w = pack2(wv.y, wv.y);
                    hacc[1][0] = ffma2(w, x01, hacc[1][0]);
                    hacc[1][1] = ffma2(w, x23, hacc[1][1]);
                    w = pack2(wv.z, wv.z);
                    hacc[2][0] = ffma2(w, x01, hacc[2][0]);
                    hacc[2][1] = ffma2(w, x23, hacc[2][1]);
                    w = pack2(wv.w, wv.w);
                    hacc[3][0] = ffma2(w, x01, hacc[3][0]);
                    hacc[3][1] = ffma2(w, x23, hacc[3][1]);
                }
                #pragma unroll
                for (int i = 0; i < 4; i++) {
                    float4 o4;
                    unpack2(hacc[i][0], o4.x, o4.y);
                    unpack2(hacc[i][1], o4.z, o4.w);
                    *(float4*)&hsm[(hty * 4 + i) * XROW + px] = o4;
                }
            }
        }
        __syncthreads();

        // ---- depthwise 3x3 + LeakyReLU: warp-per-channel mapping ----
        #pragma unroll
        for (int ii = 0; ii < 2; ii++) {
            int c = wrp * 2 + ii;
            float kr[9];
            #pragma unroll
            for (int j = 0; j < 9; j++) kr[j] = dks[(cc + c) * 9 + j];
            const float* hc = &hsm[c * XROW];
            #pragma unroll
            for (int i = 0; i < 8; i++) {
                int hp = (i + 1) * 34 + lane + 1;
                float y =
                    kr[0] * hc[hp - 35] + kr[1] * hc[hp - 34] + kr[2] * hc[hp - 33] +
                    kr[3] * hc[hp - 1]  + kr[4] * hc[hp]      + kr[5] * hc[hp + 1]  +
                    kr[6] * hc[hp + 33] + kr[7] * hc[hp + 34] + kr[8] * hc[hp + 35];
                ylc[c * YROW + i * 32 + lane] = y > 0.f ? y : 0.1f * y;
            }
        }
        __syncthreads();

        // ---- out-projection accumulate, f32x2 (o-pairs) ----
        #pragma unroll 4
        for (int c = 0; c < CHK; c++) {
            float4 y = *(const float4*)&ylc[c * YROW + lx * 4];
            u64 yd0 = pack2(y.x, y.x), yd1 = pack2(y.y, y.y);
            u64 yd2 = pack2(y.z, y.z), yd3 = pack2(y.w, y.w);
            ulonglong2 wp = *(const ulonglong2*)&wt[(cc + c) * 68 + ly * 8];
            ulonglong2 wq = *(const ulonglong2*)&wt[(cc + c) * 68 + ly * 8 + 4];
            acc2[0][0] = ffma2(wp.x, yd0, acc2[0][0]);
            acc2[0][1] = ffma2(wp.x, yd1, acc2[0][1]);
            acc2[0][2] = ffma2(wp.x, yd2, acc2[0][2]);
            acc2[0][3] = ffma2(wp.x, yd3, acc2[0][3]);
            acc2[1][0] = ffma2(wp.y, yd0, acc2[1][0]);
            acc2[1][1] = ffma2(wp.y, yd1, acc2[1][1]);
            acc2[1][2] = ffma2(wp.y, yd2, acc2[1][2]);
            acc2[1][3] = ffma2(wp.y, yd3, acc2[1][3]);
            acc2[2][0] = ffma2(wq.x, yd0, acc2[2][0]);
            acc2[2][1] = ffma2(wq.x, yd1, acc2[2][1]);
            acc2[2][2] = ffma2(wq.x, yd2, acc2[2][2]);
            acc2[2][3] = ffma2(wq.x, yd3, acc2[2][3]);
            acc2[3][0] = ffma2(wq.y, yd0, acc2[3][0]);
            acc2[3][1] = ffma2(wq.y, yd1, acc2[3][1]);
            acc2[3][2] = ffma2(wq.y, yd2, acc2[3][2]);
            acc2[3][3] = ffma2(wq.y, yd3, acc2[3][3]);
        }
    }

    // unpack + write out (+b_out). px strip = lx*4 (4 consecutive px).
    float vals[8][4];
    #pragma unroll
    for (int op = 0; op < 4; op++)
        #pragma unroll
        for (int j = 0; j < 4; j++)
            unpack2(acc2[op][j], vals[op * 2][j], vals[op * 2 + 1][j]);

    int px = lx * 4;
    int py = px >> 5, pxx = px & 31;
    #pragma unroll
    for (int i = 0; i < 8; i++) {
        int o = ly * 8 + i;
        float bo = __ldg(&b_out[o]);
        size_t base = (size_t)(b * CIN + o) * PIX + (ty0 + py) * WW + tx0 + pxx;
        *(float4*)&out[base] = make_float4(vals[i][0] + bo, vals[i][1] + bo,
                                           vals[i][2] + bo, vals[i][3] + bo);
    }
}

// ---------------------------------------------------------------------------
extern "C" void kernel_launch(void* const* d_in, const int* in_sizes, int n_in,
                              void* d_out, int out_size) {
    const float* x     = (const float*)d_in[0];
    const float* w_in  = (const float*)d_in[1];
    const float* b_in  = (const float*)d_in[2];
    const float* wg1   = (const float*)d_in[3];
    const float* bg1   = (const float*)d_in[4];
    const float* wg2   = (const float*)d_in[5];
    const float* bg2   = (const float*)d_in[6];
    const float* w_out = (const float*)d_in[7];
    const float* b_out = (const float*)d_in[8];
    float* out = (float*)d_out;

    k_xmean<<<NB * CIN, 256>>>(x);
    k_genAB<<<1, 256>>>(w_in, b_in, wg1, bg1);
    k_genC<<<36, 256>>>(wg2, bg2);

    int smem = (64 * XROW + 64 * 36 + 128 * 68 + 1152 +
                CHK * XROW + CHK * YROW) * 4;   // 214528 B
    cudaFuncSetAttribute(k_fused, cudaFuncAttributeMaxDynamicSharedMemorySize, smem);
    k_fused<<<dim3(WW / 32, HH / 8, NB), 512, smem>>>(
        x, w_in, b_in, w_out, b_out, out);
}

// round 4
// speedup vs baseline: 2.2444x; 1.0030x over previous
#include <cuda_runtime.h>

#define NB   8
#define CIN  64
#define HID  128
#define HH   192
#define WW   192
#define PIX  (HH*WW)   /* 36864 */

typedef unsigned long long u64;

__device__ __forceinline__ u64 pack2(float lo, float hi) {
    u64 d;
    asm("mov.b64 %0, {%1,%2};" : "=l"(d)
        : "r"(__float_as_uint(lo)), "r"(__float_as_uint(hi)));
    return d;
}
__device__ __forceinline__ void unpack2(u64 v, float& lo, float& hi) {
    unsigned a, b;
    asm("mov.b64 {%0,%1}, %2;" : "=r"(a), "=r"(b) : "l"(v));
    lo = __uint_as_float(a); hi = __uint_as_float(b);
}
__device__ __forceinline__ u64 ffma2(u64 a, u64 b, u64 c) {
    u64 d;
    asm("fma.rn.f32x2 %0, %1, %2, %3;" : "=l"(d) : "l"(a), "l"(b), "l"(c));
    return d;
}

// scratch (allocation-guard-safe __device__ globals)
__device__ float g_xmean[NB * CIN];
__device__ float g_gg[NB * HID];
__device__ float g_dk[NB * HID * 9];

// ---------------------------------------------------------------------------
// K1: per-(b,c) mean of x (mean(h) = W_in @ mean(x) + b_in by linearity).
// ---------------------------------------------------------------------------
__global__ __launch_bounds__(256) void k_xmean(const float* __restrict__ x) {
    int bc = blockIdx.x;
    const float4* xp = (const float4*)(x + (size_t)bc * PIX);
    float s = 0.f;
    for (int i = threadIdx.x; i < PIX / 4; i += 256) {
        float4 v = xp[i];
        s += (v.x + v.y) + (v.z + v.w);
    }
    __shared__ float red[256];
    red[threadIdx.x] = s;
    __syncthreads();
    for (int off = 128; off > 0; off >>= 1) {
        if (threadIdx.x < off) red[threadIdx.x] += red[threadIdx.x + off];
        __syncthreads();
    }
    if (threadIdx.x == 0) g_xmean[bc] = red[0] * (1.0f / PIX);
}

// ---------------------------------------------------------------------------
// K2a: hmean -> relu(wg1 @ hmean + bg1) = gg. Tiny, 1 block.
// ---------------------------------------------------------------------------
__global__ __launch_bounds__(256) void k_genAB(
    const float* __restrict__ w_in, const float* __restrict__ b_in,
    const float* __restrict__ wg1,  const float* __restrict__ bg1) {
    __shared__ float hm[NB * HID];
    int tid = threadIdx.x;
    for (int idx = tid; idx < NB * HID; idx += 256) {
        int b = idx / HID, o = idx % HID;
        float s = b_in[o];
        #pragma unroll 16
        for (int c = 0; c < CIN; c++) s += w_in[o * CIN + c] * g_xmean[b * CIN + c];
        hm[idx] = s;
    }
    __syncthreads();
    for (int idx = tid; idx < NB * HID; idx += 256) {
        int b = idx / HID, j = idx % HID;
        float s = bg1[j];
        const float4* wr = (const float4*)&wg1[j * HID];
        const float4* hr = (const float4*)&hm[b * HID];
        #pragma unroll 8
        for (int o = 0; o < HID / 4; o++) {
            float4 w = wr[o], h = hr[o];
            s += w.x * h.x + w.y * h.y + w.z * h.z + w.w * h.w;
        }
        g_gg[idx] = s > 0.f ? s : 0.f;
    }
}

// ---------------------------------------------------------------------------
// K2b: dk = wg2 @ gg + bg2. 36 blocks; wg2 staged coalesced; read once.
// ---------------------------------------------------------------------------
__global__ __launch_bounds__(256) void k_genC(
    const float* __restrict__ wg2, const float* __restrict__ bg2) {
    __shared__ float w2s[32 * 128];
    __shared__ float ggs[NB * HID];
    int tid = threadIdx.x;
    int m0 = blockIdx.x * 32;
    for (int idx = tid; idx < 32 * 128 / 4; idx += 256)
        *(float4*)&w2s[idx * 4] = *(const float4*)&wg2[(size_t)m0 * HID + idx * 4];
    for (int idx = tid; idx < NB * HID / 4; idx += 256)
        *(float4*)&ggs[idx * 4] = *(const float4*)&g_gg[idx * 4];
    __syncthreads();
    int ml = tid >> 3, b = tid & 7;
    float s = bg2[m0 + ml];
    #pragma unroll 8
    for (int j = 0; j < HID / 4; j++) {
        float4 w = *(const float4*)&w2s[ml * 128 + j * 4];
        float4 g = *(const float4*)&ggs[b * HID + j * 4];
        s += w.x * g.x + w.y * g.y + w.z * g.z + w.w * g.w;
    }
    g_dk[b * HID * 9 + m0 + ml] = s;
}

// ---------------------------------------------------------------------------
// K3: fused h=W_in@x -> per-sample dw3x3 + LeakyReLU -> out=W_out@y + b_out.
// 512 threads/block (16 warps/SM), f32x2 packed FMA in both GEMMs.
// ---------------------------------------------------------------------------
#define XROW 344   /* 34*10=340 used */
#define YROW 264   /* 256 used */
#define CHK  32

__global__ __launch_bounds__(512) void k_fused(
    const float* __restrict__ x, const float* __restrict__ w_in,
    const float* __restrict__ b_in, const float* __restrict__ w_out,
    const float* __restrict__ b_out, float* __restrict__ out) {
    extern __shared__ float sm[];
    float* xs  = sm;                    // [64][344]  x halo tile
    float* wsT = xs  + 64 * XROW;       // [64][36]   w_in chunk^T
    float* wt  = wsT + 64 * 36;         // [128][68]  w_out^T
    float* dks = wt  + 128 * 68;        // [1152]
    float* hsm = dks + 1152;            // [32][344]
    float* ylc = hsm + CHK * XROW;      // [32][264]

    int b   = blockIdx.z;
    int tx0 = blockIdx.x * 32;
    int ty0 = blockIdx.y * 8;
    int tid = threadIdx.x;

    // one-time loads
    for (int idx = tid; idx < CIN * HID; idx += 512) {
        int c = idx >> 6, o = idx & 63;
        wt[c * 68 + o] = w_out[o * HID + c];
    }
    for (int idx = tid; idx < HID * 9; idx += 512)
        dks[idx] = g_dk[b * HID * 9 + idx];
    for (int idx = tid; idx < 64 * 340; idx += 512) {
        int c = idx / 340, hp = idx - c * 340;
        int hy = hp / 34,  hx = hp - hy * 34;
        int gy = ty0 + hy - 1, gx = tx0 + hx - 1;
        float v = 0.f;
        if (gy >= 0 && gy < HH && gx >= 0 && gx < WW)
            v = x[(size_t)(b * CIN + c) * PIX + gy * WW + gx];
        xs[c * XROW + hp] = v;
    }

    int lx = tid & 63;      // out-proj: 4-px strip (conflict-free float4)
    int ly = tid >> 6;      // out-proj: 8-o strip
    int hty = tid >> 6;     // h-GEMM: 4-channel group
    int l64 = tid & 63;
    int lane = tid & 31, wrp = tid >> 5;

    u64 acc2[4][4];         // o-pairs x px, packed f32x2
    #pragma unroll
    for (int i = 0; i < 4; i++)
        #pragma unroll
        for (int j = 0; j < 4; j++) acc2[i][j] = 0ULL;

    for (int cc = 0; cc < HID; cc += CHK) {
        __syncthreads();
        // w_in chunk transposed (coalesced LDG)
        for (int idx = tid; idx < 64 * CHK; idx += 512) {
            int c = idx & 63, ch = idx >> 6;
            wsT[c * 36 + ch] = w_in[(cc + ch) * CIN + c];
        }
        __syncthreads();

        // ---- h GEMM on halo grid, f32x2 (px-pairs) ----
        #pragma unroll
        for (int pass = 0; pass < 2; pass++) {
            int pg = l64 + pass * 64;
            if (pg < 85) {
                int px = pg << 2;
                u64 hacc[4][2];
                #pragma unroll
                for (int i = 0; i < 4; i++) {
                    float bi = __ldg(&b_in[cc + hty * 4 + i]);
                    hacc[i][0] = pack2(bi, bi);
                    hacc[i][1] = hacc[i][0];
                }
                #pragma unroll 8
                for (int c = 0; c < CIN; c++) {
                    float4 xv = *(const float4*)&xs[c * XROW + px];
                    u64 x01 = pack2(xv.x, xv.y);
                    u64 x23 = pack2(xv.z, xv.w);
                    float4 wv = *(const float4*)&wsT[c * 36 + hty * 4];
                    u64 w;
                    w = pack2(wv.x, wv.x);
                    hacc[0][0] = ffma2(w, x01, hacc[0][0]);
                    hacc[0][1] = ffma2(w, x23, hacc[0][1]);
                    w = pack2(wv.y, wv.y);
                    hacc[1][0] = ffma2(w, x01, hacc[1][0]);
                    hacc[1][1] = ffma2(w, x23, hacc[1][1]);
                    w = pack2(wv.z, wv.z);
                    hacc[2][0] = ffma2(w, x01, hacc[2][0]);
                    hacc[2][1] = ffma2(w, x23, hacc[2][1]);
                    w = pack2(wv.w, wv.w);
                    hacc[3][0] = ffma2(w, x01, hacc[3][0]);
                    hacc[3][1] = ffma2(w, x23, hacc[3][1]);
                }
                #pragma unroll
                for (int i = 0; i < 4; i++) {
                    float4 o4;
                    unpack2(hacc[i][0], o4.x, o4.y);
                    unpack2(hacc[i][1], o4.z, o4.w);
                    *(float4*)&hsm[(hty * 4 + i) * XROW + px] = o4;
                }
            }
        }
        __syncthreads();

        // ---- depthwise 3x3 + LeakyReLU: warp-per-channel mapping ----
        #pragma unroll
        for (int ii = 0; ii < 2; ii++) {
            int c = wrp * 2 + ii;
            float kr[9];
            #pragma unroll
            for (int j = 0; j < 9; j++) kr[j] = dks[(cc + c) * 9 + j];
            const float* hc = &hsm[c * XROW];
            #pragma unroll
            for (int i = 0; i < 8; i++) {
                int hp = (i + 1) * 34 + lane + 1;
                float y =
                    kr[0] * hc[hp - 35] + kr[1] * hc[hp - 34] + kr[2] * hc[hp - 33] +
                    kr[3] * hc[hp - 1]  + kr[4] * hc[hp]      + kr[5] * hc[hp + 1]  +
                    kr[6] * hc[hp + 33] + kr[7] * hc[hp + 34] + kr[8] * hc[hp + 35];
                ylc[c * YROW + i * 32 + lane] = y > 0.f ? y : 0.1f * y;
            }
        }
        __syncthreads();

        // ---- out-projection accumulate, f32x2 (o-pairs) ----
        #pragma unroll 4
        for (int c = 0; c < CHK; c++) {
            float4 y = *(const float4*)&ylc[c * YROW + lx * 4];
            u64 yd0 = pack2(y.x, y.x), yd1 = pack2(y.y, y.y);
            u64 yd2 = pack2(y.z, y.z), yd3 = pack2(y.w, y.w);
            ulonglong2 wp = *(const ulonglong2*)&wt[(cc + c) * 68 + ly * 8];
            ulonglong2 wq = *(const ulonglong2*)&wt[(cc + c) * 68 + ly * 8 + 4];
            acc2[0][0] = ffma2(wp.x, yd0, acc2[0][0]);
            acc2[0][1] = ffma2(wp.x, yd1, acc2[0][1]);
            acc2[0][2] = ffma2(wp.x, yd2, acc2[0][2]);
            acc2[0][3] = ffma2(wp.x, yd3, acc2[0][3]);
            acc2[1][0] = ffma2(wp.y, yd0, acc2[1][0]);
            acc2[1][1] = ffma2(wp.y, yd1, acc2[1][1]);
            acc2[1][2] = ffma2(wp.y, yd2, acc2[1][2]);
            acc2[1][3] = ffma2(wp.y, yd3, acc2[1][3]);
            acc2[2][0] = ffma2(wq.x, yd0, acc2[2][0]);
            acc2[2][1] = ffma2(wq.x, yd1, acc2[2][1]);
            acc2[2][2] = ffma2(wq.x, yd2, acc2[2][2]);
            acc2[2][3] = ffma2(wq.x, yd3, acc2[2][3]);
            acc2[3][0] = ffma2(wq.y, yd0, acc2[3][0]);
            acc2[3][1] = ffma2(wq.y, yd1, acc2[3][1]);
            acc2[3][2] = ffma2(wq.y, yd2, acc2[3][2]);
            acc2[3][3] = ffma2(wq.y, yd3, acc2[3][3]);
        }
    }

    // unpack + write out (+b_out). px strip = lx*4 (4 consecutive px).
    float vals[8][4];
    #pragma unroll
    for (int op = 0; op < 4; op++)
        #pragma unroll
        for (int j = 0; j < 4; j++)
            unpack2(acc2[op][j], vals[op * 2][j], vals[op * 2 + 1][j]);

    int px = lx * 4;
    int py = px >> 5, pxx = px & 31;
    #pragma unroll
    for (int i = 0; i < 8; i++) {
        int o = ly * 8 + i;
        float bo = __ldg(&b_out[o]);
        size_t base = (size_t)(b * CIN + o) * PIX + (ty0 + py) * WW + tx0 + pxx;
        *(float4*)&out[base] = make_float4(vals[i][0] + bo, vals[i][1] + bo,
                                           vals[i][2] + bo, vals[i][3] + bo);
    }
}

// ---------------------------------------------------------------------------
extern "C" void kernel_launch(void* const* d_in, const int* in_sizes, int n_in,
                              void* d_out, int out_size) {
    const float* x     = (const float*)d_in[0];
    const float* w_in  = (const float*)d_in[1];
    const float* b_in  = (const float*)d_in[2];
    const float* wg1   = (const float*)d_in[3];
    const float* bg1   = (const float*)d_in[4];
    const float* wg2   = (const float*)d_in[5];
    const float* bg2   = (const float*)d_in[6];
    const float* w_out = (const float*)d_in[7];
    const float* b_out = (const float*)d_in[8];
    float* out = (float*)d_out;

    k_xmean<<<NB * CIN, 256>>>(x);
    k_genAB<<<1, 256>>>(w_in, b_in, wg1, bg1);
    k_genC<<<36, 256>>>(wg2, bg2);

    int smem = (64 * XROW + 64 * 36 + 128 * 68 + 1152 +
                CHK * XROW + CHK * YROW) * 4;   // 214528 B
    cudaFuncSetAttribute(k_fused, cudaFuncAttributeMaxDynamicSharedMemorySize, smem);
    k_fused<<<dim3(WW / 32, HH / 8, NB), 512, smem>>>(
        x, w_in, b_in, w_out, b_out, out);
}

// round 5
// speedup vs baseline: 2.2445x; 1.0001x over previous
#include <cuda_runtime.h>

#define NB   8
#define CIN  64
#define HID  128
#define HH   192
#define WW   192
#define PIX  (HH*WW)   /* 36864 */

typedef unsigned long long u64;

__device__ __forceinline__ u64 pack2(float lo, float hi) {
    u64 d;
    asm("mov.b64 %0, {%1,%2};" : "=l"(d)
        : "r"(__float_as_uint(lo)), "r"(__float_as_uint(hi)));
    return d;
}
__device__ __forceinline__ void unpack2(u64 v, float& lo, float& hi) {
    unsigned a, b;
    asm("mov.b64 {%0,%1}, %2;" : "=r"(a), "=r"(b) : "l"(v));
    lo = __uint_as_float(a); hi = __uint_as_float(b);
}
__device__ __forceinline__ u64 ffma2(u64 a, u64 b, u64 c) {
    u64 d;
    asm("fma.rn.f32x2 %0, %1, %2, %3;" : "=l"(d) : "l"(a), "l"(b), "l"(c));
    return d;
}

// scratch (allocation-guard-safe __device__ globals)
__device__ float g_xmean[NB * CIN];
__device__ float g_gg[NB * HID];
__device__ float g_dk[NB * HID * 9];

// ---------------------------------------------------------------------------
// K1: per-(b,c) mean of x (mean(h) = W_in @ mean(x) + b_in by linearity).
// ---------------------------------------------------------------------------
__global__ __launch_bounds__(256) void k_xmean(const float* __restrict__ x) {
    int bc = blockIdx.x;
    const float4* xp = (const float4*)(x + (size_t)bc * PIX);
    float s = 0.f;
    for (int i = threadIdx.x; i < PIX / 4; i += 256) {
        float4 v = xp[i];
        s += (v.x + v.y) + (v.z + v.w);
    }
    __shared__ float red[256];
    red[threadIdx.x] = s;
    __syncthreads();
    for (int off = 128; off > 0; off >>= 1) {
        if (threadIdx.x < off) red[threadIdx.x] += red[threadIdx.x + off];
        __syncthreads();
    }
    if (threadIdx.x == 0) g_xmean[bc] = red[0] * (1.0f / PIX);
}

// ---------------------------------------------------------------------------
// K2a: hmean -> relu(wg1 @ hmean + bg1) = gg. Tiny, 1 block.
// ---------------------------------------------------------------------------
__global__ __launch_bounds__(256) void k_genAB(
    const float* __restrict__ w_in, const float* __restrict__ b_in,
    const float* __restrict__ wg1,  const float* __restrict__ bg1) {
    __shared__ float hm[NB * HID];
    int tid = threadIdx.x;
    for (int idx = tid; idx < NB * HID; idx += 256) {
        int b = idx / HID, o = idx % HID;
        float s = b_in[o];
        #pragma unroll 16
        for (int c = 0; c < CIN; c++) s += w_in[o * CIN + c] * g_xmean[b * CIN + c];
        hm[idx] = s;
    }
    __syncthreads();
    for (int idx = tid; idx < NB * HID; idx += 256) {
        int b = idx / HID, j = idx % HID;
        float s = bg1[j];
        const float4* wr = (const float4*)&wg1[j * HID];
        const float4* hr = (const float4*)&hm[b * HID];
        #pragma unroll 8
        for (int o = 0; o < HID / 4; o++) {
            float4 w = wr[o], h = hr[o];
            s += w.x * h.x + w.y * h.y + w.z * h.z + w.w * h.w;
        }
        g_gg[idx] = s > 0.f ? s : 0.f;
    }
}

// ---------------------------------------------------------------------------
// K2b: dk = wg2 @ gg + bg2. 36 blocks; wg2 staged coalesced; read once.
// ---------------------------------------------------------------------------
__global__ __launch_bounds__(256) void k_genC(
    const float* __restrict__ wg2, const float* __restrict__ bg2) {
    __shared__ float w2s[32 * 128];
    __shared__ float ggs[NB * HID];
    int tid = threadIdx.x;
    int m0 = blockIdx.x * 32;
    for (int idx = tid; idx < 32 * 128 / 4; idx += 256)
        *(float4*)&w2s[idx * 4] = *(const float4*)&wg2[(size_t)m0 * HID + idx * 4];
    for (int idx = tid; idx < NB * HID / 4; idx += 256)
        *(float4*)&ggs[idx * 4] = *(const float4*)&g_gg[idx * 4];
    __syncthreads();
    int ml = tid >> 3, b = tid & 7;
    float s = bg2[m0 + ml];
    #pragma unroll 8
    for (int j = 0; j < HID / 4; j++) {
        float4 w = *(const float4*)&w2s[ml * 128 + j * 4];
        float4 g = *(const float4*)&ggs[b * HID + j * 4];
        s += w.x * g.x + w.y * g.y + w.z * g.z + w.w * g.w;
    }
    g_dk[b * HID * 9 + m0 + ml] = s;
}

// ---------------------------------------------------------------------------
// K3: fused h=W_in@x -> per-sample dw3x3 + LeakyReLU -> out=W_out@y + b_out.
// 512 threads/block (16 warps/SM), f32x2 packed FMA in both GEMMs.
// ---------------------------------------------------------------------------
#define XROW 344   /* 34*10=340 used */
#define YROW 264   /* 256 used */
#define CHK  32

__global__ __launch_bounds__(512) void k_fused(
    const float* __restrict__ x, const float* __restrict__ w_in,
    const float* __restrict__ b_in, const float* __restrict__ w_out,
    const float* __restrict__ b_out, float* __restrict__ out) {
    extern __shared__ float sm[];
    float* xs  = sm;                    // [64][344]  x halo tile
    float* wsT = xs  + 64 * XROW;       // [64][36]   w_in chunk^T
    float* wt  = wsT + 64 * 36;         // [128][68]  w_out^T
    float* dks = wt  + 128 * 68;        // [1152]
    float* hsm = dks + 1152;            // [32][344]
    float* ylc = hsm + CHK * XROW;      // [32][264]

    int b   = blockIdx.z;
    int tx0 = blockIdx.x * 32;
    int ty0 = blockIdx.y * 8;
    int tid = threadIdx.x;

    // one-time loads
    for (int idx = tid; idx < CIN * HID; idx += 512) {
        int c = idx >> 6, o = idx & 63;
        wt[c * 68 + o] = w_out[o * HID + c];
    }
    for (int idx = tid; idx < HID * 9; idx += 512)
        dks[idx] = g_dk[b * HID * 9 + idx];
    for (int idx = tid; idx < 64 * 340; idx += 512) {
        int c = idx / 340, hp = idx - c * 340;
        int hy = hp / 34,  hx = hp - hy * 34;
        int gy = ty0 + hy - 1, gx = tx0 + hx - 1;
        float v = 0.f;
        if (gy >= 0 && gy < HH && gx >= 0 && gx < WW)
            v = x[(size_t)(b * CIN + c) * PIX + gy * WW + gx];
        xs[c * XROW + hp] = v;
    }

    int lx = tid & 63;      // out-proj: 4-px strip (conflict-free float4)
    int ly = tid >> 6;      // out-proj: 8-o strip
    int hty = tid >> 6;     // h-GEMM: 4-channel group
    int l64 = tid & 63;
    int lane = tid & 31, wrp = tid >> 5;

    u64 acc2[4][4];         // o-pairs x px, packed f32x2
    #pragma unroll
    for (int i = 0; i < 4; i++)
        #pragma unroll
        for (int j = 0; j < 4; j++) acc2[i][j] = 0ULL;

    for (int cc = 0; cc < HID; cc += CHK) {
        __syncthreads();
        // w_in chunk transposed (coalesced LDG)
        for (int idx = tid; idx < 64 * CHK; idx += 512) {
            int c = idx & 63, ch = idx >> 6;
            wsT[c * 36 + ch] = w_in[(cc + ch) * CIN + c];
        }
        __syncthreads();

        // ---- h GEMM on halo grid, f32x2 (px-pairs) ----
        #pragma unroll
        for (int pass = 0; pass < 2; pass++) {
            int pg = l64 + pass * 64;
            if (pg < 85) {
                int px = pg << 2;
                u64 hacc[4][2];
                #pragma unroll
                for (int i = 0; i < 4; i++) {
                    float bi = __ldg(&b_in[cc + hty * 4 + i]);
                    hacc[i][0] = pack2(bi, bi);
                    hacc[i][1] = hacc[i][0];
                }
                #pragma unroll 8
                for (int c = 0; c < CIN; c++) {
                    float4 xv = *(const float4*)&xs[c * XROW + px];
                    u64 x01 = pack2(xv.x, xv.y);
                    u64 x23 = pack2(xv.z, xv.w);
                    float4 wv = *(const float4*)&wsT[c * 36 + hty * 4];
                    u64 w;
                    w = pack2(wv.x, wv.x);
                    hacc[0][0] = ffma2(w, x01, hacc[0][0]);
                    hacc[0][1] = ffma2(w, x23, hacc[0][1]);
                    w = pack2(wv.y, wv.y);
                    hacc[1][0] = ffma2(w, x01, hacc[1][0]);
                    hacc[1][1] = ffma2(w, x23, hacc[1][1]);
                    w = pack2(wv.z, wv.z);
                    hacc[2][0] = ffma2(w, x01, hacc[2][0]);
                    hacc[2][1] = ffma2(w, x23, hacc[2][1]);
                    w = pack2(wv.w, wv.w);
                    hacc[3][0] = ffma2(w, x01, hacc[3][0]);
                    hacc[3][1] = ffma2(w, x23, hacc[3][1]);
                }
                #pragma unroll
                for (int i = 0; i < 4; i++) {
                    float4 o4;
                    unpack2(hacc[i][0], o4.x, o4.y);
                    unpack2(hacc[i][1], o4.z, o4.w);
                    *(float4*)&hsm[(hty * 4 + i) * XROW + px] = o4;
                }
            }
        }
        __syncthreads();

        // ---- depthwise 3x3 + LeakyReLU: warp-per-channel mapping ----
        #pragma unroll
        for (int ii = 0; ii < 2; ii++) {
            int c = wrp * 2 + ii;
            float kr[9];
            #pragma unroll
            for (int j = 0; j < 9; j++) kr[j] = dks[(cc + c) * 9 + j];
            const float* hc = &hsm[c * XROW];
            #pragma unroll
            for (int i = 0; i < 8; i++) {
                int hp = (i + 1) * 34 + lane + 1;
                float y =
                    kr[0] * hc[hp - 35] + kr[1] * hc[hp - 34] + kr[2] * hc[hp - 33] +
                    kr[3] * hc[hp - 1]  + kr[4] * hc[hp]      + kr[5] * hc[hp + 1]  +
                    kr[6] * hc[hp + 33] + kr[7] * hc[hp + 34] + kr[8] * hc[hp + 35];
                ylc[c * YROW + i * 32 + lane] = y > 0.f ? y : 0.1f * y;
            }
        }
        __syncthreads();

        // ---- out-projection accumulate, f32x2 (o-pairs) ----
        #pragma unroll 4
        for (int c = 0; c < CHK; c++) {
            float4 y = *(const float4*)&ylc[c * YROW + lx * 4];
            u64 yd0 = pack2(y.x, y.x), yd1 = pack2(y.y, y.y);
            u64 yd2 = pack2(y.z, y.z), yd3 = pack2(y.w, y.w);
            ulonglong2 wp = *(const ulonglong2*)&wt[(cc + c) * 68 + ly * 8];
            ulonglong2 wq = *(const ulonglong2*)&wt[(cc + c) * 68 + ly * 8 + 4];
            acc2[0][0] = ffma2(wp.x, yd0, acc2[0][0]);
            acc2[0][1] = ffma2(wp.x, yd1, acc2[0][1]);
            acc2[0][2] = ffma2(wp.x, yd2, acc2[0][2]);
            acc2[0][3] = ffma2(wp.x, yd3, acc2[0][3]);
            acc2[1][0] = ffma2(wp.y, yd0, acc2[1][0]);
            acc2[1][1] = ffma2(wp.y, yd1, acc2[1][1]);
            acc2[1][2] = ffma2(wp.y, yd2, acc2[1][2]);
            acc2[1][3] = ffma2(wp.y, yd3, acc2[1][3]);
            acc2[2][0] = ffma2(wq.x, yd0, acc2[2][0]);
            acc2[2][1] = ffma2(wq.x, yd1, acc2[2][1]);
            acc2[2][2] = ffma2(wq.x, yd2, acc2[2][2]);
            acc2[2][3] = ffma2(wq.x, yd3, acc2[2][3]);
            acc2[3][0] = ffma2(wq.y, yd0, acc2[3][0]);
            acc2[3][1] = ffma2(wq.y, yd1, acc2[3][1]);
            acc2[3][2] = ffma2(wq.y, yd2, acc2[3][2]);
            acc2[3][3] = ffma2(wq.y, yd3, acc2[3][3]);
        }
    }

    // unpack + write out (+b_out). px strip = lx*4 (4 consecutive px).
    float vals[8][4];
    #pragma unroll
    for (int op = 0; op < 4; op++)
        #pragma unroll
        for (int j = 0; j < 4; j++)
            unpack2(acc2[op][j], vals[op * 2][j], vals[op * 2 + 1][j]);

    int px = lx * 4;
    int py = px >> 5, pxx = px & 31;
    #pragma unroll
    for (int i = 0; i < 8; i++) {
        int o = ly * 8 + i;
        float bo = __ldg(&b_out[o]);
        size_t base = (size_t)(b * CIN + o) * PIX + (ty0 + py) * WW + tx0 + pxx;
        *(float4*)&out[base] = make_float4(vals[i][0] + bo, vals[i][1] + bo,
                                           vals[i][2] + bo, vals[i][3] + bo);
    }
}

// ---------------------------------------------------------------------------
extern "C" void kernel_launch(void* const* d_in, const int* in_sizes, int n_in,
                              void* d_out, int out_size) {
    const float* x     = (const float*)d_in[0];
    const float* w_in  = (const float*)d_in[1];
    const float* b_in  = (const float*)d_in[2];
    const float* wg1   = (const float*)d_in[3];
    const float* bg1   = (const float*)d_in[4];
    const float* wg2   = (const float*)d_in[5];
    const float* bg2   = (const float*)d_in[6];
    const float* w_out = (const float*)d_in[7];
    const float* b_out = (const float*)d_in[8];
    float* out = (float*)d_out;

    k_xmean<<<NB * CIN, 256>>>(x);
    k_genAB<<<1, 256>>>(w_in, b_in, wg1, bg1);
    k_genC<<<36, 256>>>(wg2, bg2);

    int smem = (64 * XROW + 64 * 36 + 128 * 68 + 1152 +
                CHK * XROW + CHK * YROW) * 4;   // 214528 B
    cudaFuncSetAttribute(k_fused, cudaFuncAttributeMaxDynamicSharedMemorySize, smem);
    k_fused<<<dim3(WW / 32, HH / 8, NB), 512, smem>>>(
        x, w_in, b_in, w_out, b_out, out);
}

// round 6
// speedup vs baseline: 2.4252x; 1.0805x over previous
#include <cuda_runtime.h>

#define NB   8
#define CIN  64
#define HID  128
#define HH   192
#define WW   192
#define PIX  (HH*WW)   /* 36864 */

typedef unsigned long long u64;

__device__ __forceinline__ u64 pack2(float lo, float hi) {
    u64 d;
    asm("mov.b64 %0, {%1,%2};" : "=l"(d)
        : "r"(__float_as_uint(lo)), "r"(__float_as_uint(hi)));
    return d;
}
__device__ __forceinline__ void unpack2(u64 v, float& lo, float& hi) {
    unsigned a, b;
    asm("mov.b64 {%0,%1}, %2;" : "=r"(a), "=r"(b) : "l"(v));
    lo = __uint_as_float(a); hi = __uint_as_float(b);
}
__device__ __forceinline__ u64 ffma2(u64 a, u64 b, u64 c) {
    u64 d;
    asm("fma.rn.f32x2 %0, %1, %2, %3;" : "=l"(d) : "l"(a), "l"(b), "l"(c));
    return d;
}

// scratch (allocation-guard-safe __device__ globals)
__device__ float g_xmean[NB * CIN];
__device__ float g_gg[NB * HID];
__device__ float g_dk[NB * HID * 9];

// ---------------------------------------------------------------------------
// K1: per-(b,c) mean of x (mean(h) = W_in @ mean(x) + b_in by linearity).
// ---------------------------------------------------------------------------
__global__ __launch_bounds__(256) void k_xmean(const float* __restrict__ x) {
    int bc = blockIdx.x;
    const float4* xp = (const float4*)(x + (size_t)bc * PIX);
    float s = 0.f;
    for (int i = threadIdx.x; i < PIX / 4; i += 256) {
        float4 v = xp[i];
        s += (v.x + v.y) + (v.z + v.w);
    }
    __shared__ float red[256];
    red[threadIdx.x] = s;
    __syncthreads();
    for (int off = 128; off > 0; off >>= 1) {
        if (threadIdx.x < off) red[threadIdx.x] += red[threadIdx.x + off];
        __syncthreads();
    }
    if (threadIdx.x == 0) g_xmean[bc] = red[0] * (1.0f / PIX);
}

// ---------------------------------------------------------------------------
// K2a: hmean -> relu(wg1 @ hmean + bg1) = gg. 4 blocks; hm recomputed
// redundantly per block (cheap), gg output sliced.
// ---------------------------------------------------------------------------
__global__ __launch_bounds__(256) void k_genAB(
    const float* __restrict__ w_in, const float* __restrict__ b_in,
    const float* __restrict__ wg1,  const float* __restrict__ bg1) {
    __shared__ float hm[NB * HID];
    int tid = threadIdx.x;
    for (int idx = tid; idx < NB * HID; idx += 256) {
        int b = idx / HID, o = idx % HID;
        float s = b_in[o];
        #pragma unroll 16
        for (int c = 0; c < CIN; c++) s += w_in[o * CIN + c] * g_xmean[b * CIN + c];
        hm[idx] = s;
    }
    __syncthreads();
    int idx = blockIdx.x * 256 + tid;   // one gg output per thread
    int b = idx / HID, j = idx % HID;
    float s = bg1[j];
    const float4* wr = (const float4*)&wg1[j * HID];
    const float4* hr = (const float4*)&hm[b * HID];
    #pragma unroll 8
    for (int o = 0; o < HID / 4; o++) {
        float4 w = wr[o], h = hr[o];
        s += w.x * h.x + w.y * h.y + w.z * h.z + w.w * h.w;
    }
    g_gg[idx] = s > 0.f ? s : 0.f;
}

// ---------------------------------------------------------------------------
// K2b: dk = wg2 @ gg + bg2. 36 blocks; wg2 staged coalesced; read once.
// ---------------------------------------------------------------------------
__global__ __launch_bounds__(256) void k_genC(
    const float* __restrict__ wg2, const float* __restrict__ bg2) {
    __shared__ float w2s[32 * 128];
    __shared__ float ggs[NB * HID];
    int tid = threadIdx.x;
    int m0 = blockIdx.x * 32;
    for (int idx = tid; idx < 32 * 128 / 4; idx += 256)
        *(float4*)&w2s[idx * 4] = *(const float4*)&wg2[(size_t)m0 * HID + idx * 4];
    for (int idx = tid; idx < NB * HID / 4; idx += 256)
        *(float4*)&ggs[idx * 4] = *(const float4*)&g_gg[idx * 4];
    __syncthreads();
    int ml = tid >> 3, b = tid & 7;
    float s = bg2[m0 + ml];
    #pragma unroll 8
    for (int j = 0; j < HID / 4; j++) {
        float4 w = *(const float4*)&w2s[ml * 128 + j * 4];
        float4 g = *(const float4*)&ggs[b * HID + j * 4];
        s += w.x * g.x + w.y * g.y + w.z * g.z + w.w * g.w;
    }
    g_dk[b * HID * 9 + m0 + ml] = s;
}

// ---------------------------------------------------------------------------
// K3: fused h=W_in@x -> per-sample dw3x3 + LeakyReLU -> out=W_out@y + b_out.
// h-GEMM: warp-internal (4 chgrp x 8 pxgrp) tile map, 8ch x 4px per thread,
// pre-duplicated f32x2 weights in bank-permuted smem. Wavefront-minimal.
// ---------------------------------------------------------------------------
#define XROW 344   /* 34*10=340 used */
#define YROW 264   /* 256 used */
#define CHK  32

__global__ __launch_bounds__(512) void k_fused(
    const float* __restrict__ x, const float* __restrict__ w_in,
    const float* __restrict__ b_in, const float* __restrict__ w_out,
    const float* __restrict__ b_out, float* __restrict__ out) {
    extern __shared__ float sm[];
    float* xs   = sm;                         // [64][344]  x halo tile (88064B)
    u64*   w2   = (u64*)(sm + 64 * XROW);     // [64][36]u64 dup'd w_in chunk (18432B)
    float* wt   = sm + 64 * XROW + 4608;      // [128][68]  w_out^T (34816B)
    float* dks  = wt + 128 * 68;              // [1152]
    float* hsm  = dks + 1152;                 // [32][344]
    float* ylc  = hsm + CHK * XROW;           // [32][264]
    // total 55936 floats = 223744 B

    int b   = blockIdx.z;
    int tx0 = blockIdx.x * 32;
    int ty0 = blockIdx.y * 8;
    int tid = threadIdx.x;
    int lane = tid & 31, wrp = tid >> 5;

    // one-time loads
    for (int idx = tid; idx < CIN * HID; idx += 512) {
        int c = idx >> 6, o = idx & 63;
        wt[c * 68 + o] = w_out[o * HID + c];
    }
    for (int idx = tid; idx < HID * 9; idx += 512)
        dks[idx] = g_dk[b * HID * 9 + idx];
    for (int idx = tid; idx < 64 * 340; idx += 512) {
        int c = idx / 340, hp = idx - c * 340;
        int hy = hp / 34,  hx = hp - hy * 34;
        int gy = ty0 + hy - 1, gx = tx0 + hx - 1;
        float v = 0.f;
        if (gy >= 0 && gy < HH && gx >= 0 && gx < WW)
            v = x[(size_t)(b * CIN + c) * PIX + gy * WW + gx];
        xs[c * XROW + hp] = v;
    }

    // h-GEMM thread map: chgrp x pxgrp inside each warp
    int chgrp = lane >> 3;               // 0..3  -> 8 channels each
    int pxg   = wrp * 8 + (lane & 7);    // pixel float4 group, active < 85
    int px    = pxg << 2;
    bool hact = pxg < 85;

    // out-proj map
    int lx = tid & 63;      // 4-px strip
    int ly = tid >> 6;      // 8-o strip

    u64 acc2[4][4];         // persistent out accumulators (o-pairs x 4 px)
    #pragma unroll
    for (int i = 0; i < 4; i++)
        #pragma unroll
        for (int j = 0; j < 4; j++) acc2[i][j] = 0ULL;

    for (int cc = 0; cc < HID; cc += CHK) {
        __syncthreads();
        // stage dup'd w_in chunk, bank-permuted:
        // slot s = ((ch&7)>>1)*8 + (ch>>3)*2 + (ch&1)
        for (int idx = tid; idx < 64 * CHK; idx += 512) {
            int c = idx & 63, ch = idx >> 6;
            float w = w_in[(cc + ch) * CIN + c];
            int s = ((ch & 7) >> 1) * 8 + (ch >> 3) * 2 + (ch & 1);
            w2[c * 36 + s] = pack2(w, w);
        }
        __syncthreads();

        // ---- h GEMM: 8ch x 4px per thread, f32x2 ----
        if (hact) {
            u64 hacc[8][2];
            #pragma unroll
            for (int i = 0; i < 8; i++) {
                float bi = __ldg(&b_in[cc + chgrp * 8 + i]);
                hacc[i][0] = pack2(bi, bi);
                hacc[i][1] = hacc[i][0];
            }
            #pragma unroll 4
            for (int c = 0; c < CIN; c++) {
                float4 xv = *(const float4*)&xs[c * XROW + px];
                u64 x01 = pack2(xv.x, xv.y);
                u64 x23 = pack2(xv.z, xv.w);
                const u64* wrow = &w2[c * 36 + chgrp * 2];
                #pragma unroll
                for (int l = 0; l < 4; l++) {
                    ulonglong2 wl = *(const ulonglong2*)&wrow[l * 8];
                    hacc[l*2  ][0] = ffma2(wl.x, x01, hacc[l*2  ][0]);
                    hacc[l*2  ][1] = ffma2(wl.x, x23, hacc[l*2  ][1]);
                    hacc[l*2+1][0] = ffma2(wl.y, x01, hacc[l*2+1][0]);
                    hacc[l*2+1][1] = ffma2(wl.y, x23, hacc[l*2+1][1]);
                }
            }
            #pragma unroll
            for (int i = 0; i < 8; i++) {
                float4 o4;
                unpack2(hacc[i][0], o4.x, o4.y);
                unpack2(hacc[i][1], o4.z, o4.w);
                *(float4*)&hsm[(chgrp * 8 + i) * XROW + px] = o4;
            }
        }
        __syncthreads();

        // ---- depthwise 3x3 + LeakyReLU: warp-per-channel ----
        #pragma unroll
        for (int ii = 0; ii < 2; ii++) {
            int c = wrp * 2 + ii;
            float kr[9];
            #pragma unroll
            for (int j = 0; j < 9; j++) kr[j] = dks[(cc + c) * 9 + j];
            const float* hc = &hsm[c * XROW];
            #pragma unroll
            for (int i = 0; i < 8; i++) {
                int hp = (i + 1) * 34 + lane + 1;
                float y =
                    kr[0] * hc[hp - 35] + kr[1] * hc[hp - 34] + kr[2] * hc[hp - 33] +
                    kr[3] * hc[hp - 1]  + kr[4] * hc[hp]      + kr[5] * hc[hp + 1]  +
                    kr[6] * hc[hp + 33] + kr[7] * hc[hp + 34] + kr[8] * hc[hp + 35];
                ylc[c * YROW + i * 32 + lane] = y > 0.f ? y : 0.1f * y;
            }
        }
        __syncthreads();

        // ---- out-projection accumulate, f32x2 (o-pairs) ----
        #pragma unroll 4
        for (int c = 0; c < CHK; c++) {
            float4 y = *(const float4*)&ylc[c * YROW + lx * 4];
            u64 yd0 = pack2(y.x, y.x), yd1 = pack2(y.y, y.y);
            u64 yd2 = pack2(y.z, y.z), yd3 = pack2(y.w, y.w);
            ulonglong2 wp = *(const ulonglong2*)&wt[(cc + c) * 68 + ly * 8];
            ulonglong2 wq = *(const ulonglong2*)&wt[(cc + c) * 68 + ly * 8 + 4];
            acc2[0][0] = ffma2(wp.x, yd0, acc2[0][0]);
            acc2[0][1] = ffma2(wp.x, yd1, acc2[0][1]);
            acc2[0][2] = ffma2(wp.x, yd2, acc2[0][2]);
            acc2[0][3] = ffma2(wp.x, yd3, acc2[0][3]);
            acc2[1][0] = ffma2(wp.y, yd0, acc2[1][0]);
            acc2[1][1] = ffma2(wp.y, yd1, acc2[1][1]);
            acc2[1][2] = ffma2(wp.y, yd2, acc2[1][2]);
            acc2[1][3] = ffma2(wp.y, yd3, acc2[1][3]);
            acc2[2][0] = ffma2(wq.x, yd0, acc2[2][0]);
            acc2[2][1] = ffma2(wq.x, yd1, acc2[2][1]);
            acc2[2][2] = ffma2(wq.x, yd2, acc2[2][2]);
            acc2[2][3] = ffma2(wq.x, yd3, acc2[2][3]);
            acc2[3][0] = ffma2(wq.y, yd0, acc2[3][0]);
            acc2[3][1] = ffma2(wq.y, yd1, acc2[3][1]);
            acc2[3][2] = ffma2(wq.y, yd2, acc2[3][2]);
            acc2[3][3] = ffma2(wq.y, yd3, acc2[3][3]);
        }
    }

    // unpack + write out (+b_out)
    float vals[8][4];
    #pragma unroll
    for (int op = 0; op < 4; op++)
        #pragma unroll
        for (int j = 0; j < 4; j++)
            unpack2(acc2[op][j], vals[op * 2][j], vals[op * 2 + 1][j]);

    int pxo = lx * 4;
    int py = pxo >> 5, pxx = pxo & 31;
    #pragma unroll
    for (int i = 0; i < 8; i++) {
        int o = ly * 8 + i;
        float bo = __ldg(&b_out[o]);
        size_t base = (size_t)(b * CIN + o) * PIX + (ty0 + py) * WW + tx0 + pxx;
        *(float4*)&out[base] = make_float4(vals[i][0] + bo, vals[i][1] + bo,
                                           vals[i][2] + bo, vals[i][3] + bo);
    }
}

// ---------------------------------------------------------------------------
extern "C" void kernel_launch(void* const* d_in, const int* in_sizes, int n_in,
                              void* d_out, int out_size) {
    const float* x     = (const float*)d_in[0];
    const float* w_in  = (const float*)d_in[1];
    const float* b_in  = (const float*)d_in[2];
    const float* wg1   = (const float*)d_in[3];
    const float* bg1   = (const float*)d_in[4];
    const float* wg2   = (const float*)d_in[5];
    const float* bg2   = (const float*)d_in[6];
    const float* w_out = (const float*)d_in[7];
    const float* b_out = (const float*)d_in[8];
    float* out = (float*)d_out;

    k_xmean<<<NB * CIN, 256>>>(x);
    k_genAB<<<4, 256>>>(w_in, b_in, wg1, bg1);
    k_genC<<<36, 256>>>(wg2, bg2);

    int smem = 223744;
    cudaFuncSetAttribute(k_fused, cudaFuncAttributeMaxDynamicSharedMemorySize, smem);
    k_fused<<<dim3(WW / 32, HH / 8, NB), 512, smem>>>(
        x, w_in, b_in, w_out, b_out, out);
}